// round 6
// baseline (speedup 1.0000x reference)
#include <cuda_runtime.h>
#include <cstdint>
#include <math.h>

// Problem constants
#define B_DIM 2
#define CIN_DIM 512
#define L_DIM 1024
#define H_DIM 32
#define D_DIM 64
#define A_DIM 2048   // H*D
#define BH_DIM (B_DIM * H_DIM)

// Scratch
__device__ float g_q[B_DIM * A_DIM * L_DIM];
__device__ float g_k[B_DIM * A_DIM * L_DIM];
__device__ float g_v[B_DIM * A_DIM * L_DIM];
__device__ float g_h[B_DIM * A_DIM * L_DIM];
__device__ float g_z[B_DIM * A_DIM * L_DIM];
__device__ float g_mx[BH_DIM * L_DIM];
__device__ float g_is[BH_DIM * L_DIM];

enum { EPI_NONE = 0, EPI_BIAS = 1, EPI_BIAS_RELU = 2, EPI_RELU = 3 };

__device__ __forceinline__ float cvt_tf32(float x) {
    uint32_t u;
    asm("cvt.rna.tf32.f32 %0, %1;" : "=r"(u) : "f"(x));
    return __uint_as_float(u);
}
__device__ __forceinline__ uint32_t cvt_tf32_u(float x) {
    uint32_t u;
    asm("cvt.rna.tf32.f32 %0, %1;" : "=r"(u) : "f"(x));
    return u;
}

__device__ __forceinline__ void mma_tf32(float c[4], const uint32_t a[4], const uint32_t b[2]) {
    asm volatile(
        "mma.sync.aligned.m16n8k8.row.col.f32.tf32.tf32.f32 "
        "{%0,%1,%2,%3}, {%4,%5,%6,%7}, {%8,%9}, {%0,%1,%2,%3};\n"
        : "+f"(c[0]), "+f"(c[1]), "+f"(c[2]), "+f"(c[3])
        : "r"(a[0]), "r"(a[1]), "r"(a[2]), "r"(a[3]), "r"(b[0]), "r"(b[1]));
}

__device__ __forceinline__ void cp_async16(float* sptr, const float* gptr) {
    uint32_t s = (uint32_t)__cvta_generic_to_shared(sptr);
    asm volatile("cp.async.cg.shared.global [%0], [%1], 16;\n" :: "r"(s), "l"(gptr));
}
__device__ __forceinline__ void cp_commit() { asm volatile("cp.async.commit_group;\n"); }
__device__ __forceinline__ void cp_wait0() { asm volatile("cp.async.wait_group 0;\n"); }
__device__ __forceinline__ void cp_wait1() { asm volatile("cp.async.wait_group 1;\n"); }

// ============================================================================
// Batched TF32 GEMM (projections + MLP) — unchanged (passing since round 2)
// ============================================================================
template <int EPI>
__global__ __launch_bounds__(256) void gemm_tc(
    const float* __restrict__ Ag, const float* __restrict__ Bg,
    const float* __restrict__ bias, float* __restrict__ Cg,
    int M, int N, int K,
    long long Abs, long long Bbs, long long Cbs)
{
    constexpr int BM = 128, BN = 128, KC = 16;
    constexpr int ASTR = BM + 8;
    constexpr int BSTR = BN + 8;

    __shared__ float As[2][KC * ASTR];
    __shared__ float Bs[2][KC * BSTR];

    const float* Ap = Ag + (long long)blockIdx.z * Abs;
    const float* Bp = Bg + (long long)blockIdx.z * Bbs;
    float* Cp = Cg + (long long)blockIdx.z * Cbs;

    const int tid = threadIdx.x;
    const int lane = tid & 31;
    const int w = tid >> 5;
    const int wm = w & 3, wn = w >> 2;
    const int row0 = blockIdx.y * BM;
    const int col0 = blockIdx.x * BN;

    float acc[2][8][4] = {};
    float4 pa[2], pb[2];

    auto fetch = [&](int k0) {
#pragma unroll
        for (int u = 0; u < 2; ++u) {
            int idx = tid + u * 256;
            int r = idx % BM, j = idx / BM;
            pa[u] = *(const float4*)&Ap[(long long)(row0 + r) * K + k0 + 4 * j];
        }
#pragma unroll
        for (int u = 0; u < 2; ++u) {
            int idx = tid + u * 256;
            int nq = idx % (BN / 4), kk = idx / (BN / 4);
            pb[u] = *(const float4*)&Bp[(long long)(k0 + kk) * N + col0 + 4 * nq];
        }
    };

    auto stage = [&](int buf) {
#pragma unroll
        for (int u = 0; u < 2; ++u) {
            int idx = tid + u * 256;
            int r = idx % BM, j = idx / BM;
            As[buf][(4 * j + 0) * ASTR + r] = cvt_tf32(pa[u].x);
            As[buf][(4 * j + 1) * ASTR + r] = cvt_tf32(pa[u].y);
            As[buf][(4 * j + 2) * ASTR + r] = cvt_tf32(pa[u].z);
            As[buf][(4 * j + 3) * ASTR + r] = cvt_tf32(pa[u].w);
        }
#pragma unroll
        for (int u = 0; u < 2; ++u) {
            int idx = tid + u * 256;
            int nq = idx % (BN / 4), kk = idx / (BN / 4);
            float4 t;
            t.x = cvt_tf32(pb[u].x); t.y = cvt_tf32(pb[u].y);
            t.z = cvt_tf32(pb[u].z); t.w = cvt_tf32(pb[u].w);
            *(float4*)&Bs[buf][kk * BSTR + 4 * nq] = t;
        }
    };

    auto compute = [&](int buf) {
        const int row = lane >> 2, kcol = lane & 3;
#pragma unroll
        for (int ks = 0; ks < KC; ks += 8) {
            uint32_t af[2][4];
#pragma unroll
            for (int f = 0; f < 2; ++f) {
                const float* Ab = &As[buf][(ks + kcol) * ASTR + wm * 32 + f * 16 + row];
                af[f][0] = __float_as_uint(Ab[0]);
                af[f][1] = __float_as_uint(Ab[8]);
                af[f][2] = __float_as_uint(Ab[4 * ASTR]);
                af[f][3] = __float_as_uint(Ab[4 * ASTR + 8]);
            }
            uint32_t bf[8][2];
#pragma unroll
            for (int g = 0; g < 8; ++g) {
                const float* Bb = &Bs[buf][(ks + kcol) * BSTR + wn * 64 + g * 8 + row];
                bf[g][0] = __float_as_uint(Bb[0]);
                bf[g][1] = __float_as_uint(Bb[4 * BSTR]);
            }
#pragma unroll
            for (int f = 0; f < 2; ++f)
#pragma unroll
                for (int g = 0; g < 8; ++g)
                    mma_tf32(acc[f][g], af[f], bf[g]);
        }
    };

    const int nit = K / KC;
    fetch(0);
    stage(0);
    __syncthreads();
    for (int it = 0; it < nit; ++it) {
        int cur = it & 1;
        if (it + 1 < nit) fetch((it + 1) * KC);
        compute(cur);
        if (it + 1 < nit) {
            stage(cur ^ 1);
            __syncthreads();
        }
    }

#pragma unroll
    for (int f = 0; f < 2; ++f) {
        int r = row0 + wm * 32 + f * 16 + (lane >> 2);
        float b0v = 0.f, b8v = 0.f;
        if (EPI == EPI_BIAS || EPI == EPI_BIAS_RELU) { b0v = bias[r]; b8v = bias[r + 8]; }
#pragma unroll
        for (int g = 0; g < 8; ++g) {
            int c = col0 + wn * 64 + g * 8 + (lane & 3) * 2;
            float v0 = acc[f][g][0] + b0v;
            float v1 = acc[f][g][1] + b0v;
            float v2 = acc[f][g][2] + b8v;
            float v3 = acc[f][g][3] + b8v;
            if (EPI == EPI_RELU || EPI == EPI_BIAS_RELU) {
                v0 = fmaxf(v0, 0.f); v1 = fmaxf(v1, 0.f);
                v2 = fmaxf(v2, 0.f); v3 = fmaxf(v3, 0.f);
            }
            *(float2*)&Cp[(long long)r * N + c] = make_float2(v0, v1);
            *(float2*)&Cp[(long long)(r + 8) * N + c] = make_float2(v2, v3);
        }
    }
}

// ============================================================================
// Attention pass 1: softmax row stats — unchanged from round 5.
// ============================================================================
__global__ __launch_bounds__(256, 2) void attn_stats(
    const float* __restrict__ q, const float* __restrict__ k,
    float* __restrict__ gM, float* __restrict__ gIS)
{
    extern __shared__ float smem[];
    float* Qs = smem;                    // [64][136] tf32
    float* Kb[2] = { smem + 64 * 136, smem + 2 * 64 * 136 };  // raw

    const long long DL = (long long)D_DIM * L_DIM;
    const int bh = blockIdx.y;
    const int l0 = blockIdx.x * 128;
    const float* qh = q + (long long)bh * DL;
    const float* kh = k + (long long)bh * DL;
    const int tid = threadIdx.x, lane = tid & 31, w = tid >> 5;
    const int wm = w & 3, wn = w >> 2;
    const int row = lane >> 2, kq = lane & 3;

#pragma unroll
    for (int u = 0; u < 8; ++u) {
        int idx = tid + u * 256;
        int d = idx >> 5, c = (idx & 31) * 4;
        cp_async16(&Kb[0][d * 136 + c], &kh[(long long)d * L_DIM + c]);
    }
    cp_commit();

#pragma unroll
    for (int u = 0; u < 8; ++u) {
        int idx = tid + u * 256;
        int d = idx >> 5, c = (idx & 31) * 4;
        float4 t = *(const float4*)&qh[(long long)d * L_DIM + l0 + c];
        t.x = cvt_tf32(t.x); t.y = cvt_tf32(t.y);
        t.z = cvt_tf32(t.z); t.w = cvt_tf32(t.w);
        *(float4*)&Qs[d * 136 + c] = t;
    }

    float Mx[4] = { -1e30f, -1e30f, -1e30f, -1e30f };
    float Sm[4] = { 0.f, 0.f, 0.f, 0.f };

    for (int mt = 0; mt < 8; ++mt) {
        const float* Ks = Kb[mt & 1];
        cp_wait0();
        __syncthreads();
        if (mt < 7) {
            float* Kn = Kb[(mt & 1) ^ 1];
#pragma unroll
            for (int u = 0; u < 8; ++u) {
                int idx = tid + u * 256;
                int d = idx >> 5, c = (idx & 31) * 4;
                cp_async16(&Kn[d * 136 + c], &kh[(long long)d * L_DIM + (mt + 1) * 128 + c]);
            }
            cp_commit();
        }

        float acc[2][8][4] = {};
#pragma unroll
        for (int ks = 0; ks < 64; ks += 8) {
            uint32_t af[2][4];
#pragma unroll
            for (int f = 0; f < 2; ++f) {
                const float* Ab = &Qs[(ks + kq) * 136 + wm * 32 + f * 16 + row];
                af[f][0] = __float_as_uint(Ab[0]);
                af[f][1] = __float_as_uint(Ab[8]);
                af[f][2] = __float_as_uint(Ab[4 * 136]);
                af[f][3] = __float_as_uint(Ab[4 * 136 + 8]);
            }
            uint32_t bf[8][2];
#pragma unroll
            for (int g = 0; g < 8; ++g) {
                const float* Bb = &Ks[(ks + kq) * 136 + wn * 64 + g * 8 + row];
                bf[g][0] = cvt_tf32_u(Bb[0]);
                bf[g][1] = cvt_tf32_u(Bb[4 * 136]);
            }
#pragma unroll
            for (int f = 0; f < 2; ++f)
#pragma unroll
                for (int g = 0; g < 8; ++g)
                    mma_tf32(acc[f][g], af[f], bf[g]);
        }

#pragma unroll
        for (int f = 0; f < 2; ++f)
#pragma unroll
            for (int sub = 0; sub < 2; ++sub) {
                int lr = l0 + wm * 32 + f * 16 + sub * 8 + row;
                float tm = -1e30f;
#pragma unroll
                for (int g = 0; g < 8; ++g) {
                    int m = mt * 128 + wn * 64 + g * 8 + kq * 2;
                    float x0 = (acc[f][g][2 * sub]     - fabsf((float)(lr - m)))     * 0.125f;
                    float x1 = (acc[f][g][2 * sub + 1] - fabsf((float)(lr - m - 1))) * 0.125f;
                    tm = fmaxf(tm, fmaxf(x0, x1));
                }
                float ts = 0.f;
#pragma unroll
                for (int g = 0; g < 8; ++g) {
                    int m = mt * 128 + wn * 64 + g * 8 + kq * 2;
                    float x0 = (acc[f][g][2 * sub]     - fabsf((float)(lr - m)))     * 0.125f;
                    float x1 = (acc[f][g][2 * sub + 1] - fabsf((float)(lr - m - 1))) * 0.125f;
                    ts += __expf(x0 - tm) + __expf(x1 - tm);
                }
                int i = 2 * f + sub;
                float nm = fmaxf(Mx[i], tm);
                Sm[i] = Sm[i] * __expf(Mx[i] - nm) + ts * __expf(tm - nm);
                Mx[i] = nm;
            }
    }

#pragma unroll
    for (int i = 0; i < 4; ++i) {
#pragma unroll
        for (int o = 1; o <= 2; o <<= 1) {
            float oM = __shfl_xor_sync(0xffffffffu, Mx[i], o);
            float oS = __shfl_xor_sync(0xffffffffu, Sm[i], o);
            float nm = fmaxf(Mx[i], oM);
            Sm[i] = Sm[i] * __expf(Mx[i] - nm) + oS * __expf(oM - nm);
            Mx[i] = nm;
        }
    }
    __syncthreads();
    float* sM = Qs;
    float* sS = Qs + 256;
    if (kq == 0) {
#pragma unroll
        for (int f = 0; f < 2; ++f)
#pragma unroll
            for (int sub = 0; sub < 2; ++sub) {
                int rl = wm * 32 + f * 16 + sub * 8 + row;
                sM[wn * 128 + rl] = Mx[2 * f + sub];
                sS[wn * 128 + rl] = Sm[2 * f + sub];
            }
    }
    __syncthreads();
    if (tid < 128) {
        float M0 = sM[tid], M1 = sM[128 + tid];
        float S0 = sS[tid], S1 = sS[128 + tid];
        float nm = fmaxf(M0, M1);
        float S = S0 * __expf(M0 - nm) + S1 * __expf(M1 - nm);
        gM[bh * L_DIM + l0 + tid] = nm;
        gIS[bh * L_DIM + l0 + tid] = 1.0f / S;
    }
}

// ============================================================================
// Attention pass 2 (512 threads / 16 warps): O^T[m,d] = W^T @ V.
// S-MMA: 4x4 warp grid, warp tile 32(l) x 32(m), FM=2, FN=4.
// O-MMA: 4x4 warp grid, warp tile 32(m) x 16(d), FM=2, FN=2.
// Staging: 8192-float tiles / 512 threads = 4 float4 each (u < 4).
// ============================================================================
__global__ __launch_bounds__(512) void attn_out(
    const float* __restrict__ q, const float* __restrict__ k,
    const float* __restrict__ v, const float* __restrict__ gM,
    const float* __restrict__ gIS, float* __restrict__ hout)
{
    extern __shared__ float smem[];
    float* Qs = smem;                       // raw f32 [d=64][l=128] str 136
    float* Vs = Qs + 64 * 136;              // raw f32 [d=64][l=128] str 132
    float* Ks = Vs + 64 * 132;              // tf32   [d=64][m=128] str 136
    float* Ws = Ks + 64 * 136;              // tf32   [l=128][m=128] str 136

    const long long DL = (long long)D_DIM * L_DIM;
    const int bh = blockIdx.y;
    const int mb = (int)(gridDim.x - 1 - blockIdx.x);
    const int m0 = mb * 128;
    const float* qh = q + (long long)bh * DL;
    const float* kh = k + (long long)bh * DL;
    const float* vh = v + (long long)bh * DL;
    const int tid = threadIdx.x, lane = tid & 31, w = tid >> 5;
    const int wm = w & 3, wn = w >> 2;      // 4 x 4 warp grid (both MMAs)
    const int row = lane >> 2, kq = lane & 3;

    auto issueQ = [&](int lb) {
#pragma unroll
        for (int u = 0; u < 4; ++u) {
            int idx = tid + u * 512;        // 0..2047 covers full 64x128 tile
            int d = idx >> 5, c = (idx & 31) * 4;
            cp_async16(&Qs[d * 136 + c], &qh[(long long)d * L_DIM + lb * 128 + c]);
        }
        cp_commit();
    };
    auto issueV = [&](int lb) {
#pragma unroll
        for (int u = 0; u < 4; ++u) {
            int idx = tid + u * 512;
            int d = idx >> 5, c = (idx & 31) * 4;
            cp_async16(&Vs[d * 132 + c], &vh[(long long)d * L_DIM + lb * 128 + c]);
        }
        cp_commit();
    };

    issueQ(0);

    // stage K tile (persistent, tf32), full 64x128
#pragma unroll
    for (int u = 0; u < 4; ++u) {
        int idx = tid + u * 512;
        int d = idx >> 5, c = (idx & 31) * 4;
        float4 t = *(const float4*)&kh[(long long)d * L_DIM + m0 + c];
        t.x = cvt_tf32(t.x); t.y = cvt_tf32(t.y);
        t.z = cvt_tf32(t.z); t.w = cvt_tf32(t.w);
        *(float4*)&Ks[d * 136 + c] = t;
    }

    float accO[2][2][4] = {};   // O^T: m (wm, f<2 -> 32), d (wn, g<2 -> 16)

    for (int lb = 0; lb <= mb; ++lb) {
        cp_wait0();             // Q(lb) landed
        __syncthreads();        // Qs visible; prev O-MMA done -> Vs/Ws free
        issueV(lb);             // hidden behind S-MMA + weights

        // S = Q^T K : [l=128][m=128]; warp tile 32x32
        float acc[2][4][4] = {};
#pragma unroll
        for (int ks = 0; ks < 64; ks += 8) {
            uint32_t af[2][4];
#pragma unroll
            for (int f = 0; f < 2; ++f) {
                const float* Ab = &Qs[(ks + kq) * 136 + wm * 32 + f * 16 + row];
                af[f][0] = cvt_tf32_u(Ab[0]);
                af[f][1] = cvt_tf32_u(Ab[8]);
                af[f][2] = cvt_tf32_u(Ab[4 * 136]);
                af[f][3] = cvt_tf32_u(Ab[4 * 136 + 8]);
            }
            uint32_t bf[4][2];
#pragma unroll
            for (int g = 0; g < 4; ++g) {
                const float* Bb = &Ks[(ks + kq) * 136 + wn * 32 + g * 8 + row];
                bf[g][0] = __float_as_uint(Bb[0]);
                bf[g][1] = __float_as_uint(Bb[4 * 136]);
            }
#pragma unroll
            for (int f = 0; f < 2; ++f)
#pragma unroll
                for (int g = 0; g < 4; ++g)
                    mma_tf32(acc[f][g], af[f], bf[g]);
        }

        // softmax weights + triu mask -> Ws[l][m] (tf32)
#pragma unroll
        for (int f = 0; f < 2; ++f)
#pragma unroll
            for (int sub = 0; sub < 2; ++sub) {
                int lloc = wm * 32 + f * 16 + sub * 8 + row;
                int lg = lb * 128 + lloc;
                float Mrow = gM[bh * L_DIM + lg];
                float IS = gIS[bh * L_DIM + lg];
#pragma unroll
                for (int g = 0; g < 4; ++g) {
                    int c = wn * 32 + g * 8 + kq * 2;
                    int mg = m0 + c;
                    float x0 = (acc[f][g][2 * sub]     - fabsf((float)(lg - mg)))     * 0.125f;
                    float x1 = (acc[f][g][2 * sub + 1] - fabsf((float)(lg - mg - 1))) * 0.125f;
                    float w0 = __expf(x0 - Mrow) * IS;
                    float w1 = __expf(x1 - Mrow) * IS;
                    if (lb == mb) {
                        if (lg > mg)     w0 = 0.f;
                        if (lg > mg + 1) w1 = 0.f;
                    }
                    float2 t2;
                    t2.x = cvt_tf32(w0);
                    t2.y = cvt_tf32(w1);
                    *(float2*)&Ws[lloc * 136 + c] = t2;
                }
            }
        __syncthreads();        // Ws ready; Qs reads done
        if (lb < mb) { issueQ(lb + 1); cp_wait1(); }  // V(lb) done, Q(lb+1) in flight
        else         { cp_wait0(); }
        __syncthreads();        // Vs visible

        // O^T += W^T[m x l] @ V[l x d]; warp tile 32(m) x 16(d)
#pragma unroll
        for (int ks = 0; ks < 128; ks += 8) {
            uint32_t af[2][4];
#pragma unroll
            for (int f = 0; f < 2; ++f) {
                const float* Ab = &Ws[(ks + kq) * 136 + wm * 32 + f * 16 + row];
                af[f][0] = __float_as_uint(Ab[0]);
                af[f][1] = __float_as_uint(Ab[8]);
                af[f][2] = __float_as_uint(Ab[4 * 136]);
                af[f][3] = __float_as_uint(Ab[4 * 136 + 8]);
            }
            uint32_t bf[2][2];
#pragma unroll
            for (int g = 0; g < 2; ++g) {
                const float* Bb = &Vs[(wn * 16 + g * 8 + row) * 132 + ks + kq];
                bf[g][0] = cvt_tf32_u(Bb[0]);
                bf[g][1] = cvt_tf32_u(Bb[4]);
            }
#pragma unroll
            for (int f = 0; f < 2; ++f)
#pragma unroll
                for (int g = 0; g < 2; ++g)
                    mma_tf32(accO[f][g], af[f], bf[g]);
        }
    }

    // epilogue: ReLU, transpose-store h[d][m]
#pragma unroll
    for (int f = 0; f < 2; ++f) {
        int rm = m0 + wm * 32 + f * 16 + row;
#pragma unroll
        for (int g = 0; g < 2; ++g) {
            int cd = wn * 16 + g * 8 + kq * 2;
            hout[(long long)bh * DL + (long long)cd * L_DIM + rm]           = fmaxf(accO[f][g][0], 0.f);
            hout[(long long)bh * DL + (long long)(cd + 1) * L_DIM + rm]     = fmaxf(accO[f][g][1], 0.f);
            hout[(long long)bh * DL + (long long)cd * L_DIM + rm + 8]       = fmaxf(accO[f][g][2], 0.f);
            hout[(long long)bh * DL + (long long)(cd + 1) * L_DIM + rm + 8] = fmaxf(accO[f][g][3], 0.f);
        }
    }
}

// ============================================================================
extern "C" void kernel_launch(void* const* d_in, const int* in_sizes, int n_in,
                              void* d_out, int out_size)
{
    (void)in_sizes; (void)n_in; (void)out_size;
    const float* x  = (const float*)d_in[0];
    const float* Wq = (const float*)d_in[1];
    const float* bq = (const float*)d_in[2];
    const float* Wk = (const float*)d_in[3];
    const float* bk = (const float*)d_in[4];
    const float* Wv = (const float*)d_in[5];
    const float* bv = (const float*)d_in[6];
    const float* W1 = (const float*)d_in[7];
    const float* b1 = (const float*)d_in[8];
    const float* W2 = (const float*)d_in[9];
    const float* b2 = (const float*)d_in[10];
    float* out = (float*)d_out;

    float *q, *k, *v, *h, *z, *mx, *is;
    cudaGetSymbolAddress((void**)&q, g_q);
    cudaGetSymbolAddress((void**)&k, g_k);
    cudaGetSymbolAddress((void**)&v, g_v);
    cudaGetSymbolAddress((void**)&h, g_h);
    cudaGetSymbolAddress((void**)&z, g_z);
    cudaGetSymbolAddress((void**)&mx, g_mx);
    cudaGetSymbolAddress((void**)&is, g_is);

    const long long AL = (long long)A_DIM * L_DIM;
    const long long XL = (long long)CIN_DIM * L_DIM;

    const int SMEM1 = (64 * 136 * 3) * 4;                                // 104448 B
    const int SMEM2 = (64 * 136 + 64 * 132 + 64 * 136 + 128 * 136) * 4;  // 173056 B
    cudaFuncSetAttribute(attn_stats, cudaFuncAttributeMaxDynamicSharedMemorySize, SMEM1);
    cudaFuncSetAttribute(attn_out,   cudaFuncAttributeMaxDynamicSharedMemorySize, SMEM2);

    // 1) QKV projections
    dim3 gproj(L_DIM / 128, A_DIM / 128, B_DIM);
    gemm_tc<EPI_BIAS><<<gproj, 256>>>(Wq, x, bq, q, A_DIM, L_DIM, CIN_DIM, 0, XL, AL);
    gemm_tc<EPI_BIAS><<<gproj, 256>>>(Wk, x, bk, k, A_DIM, L_DIM, CIN_DIM, 0, XL, AL);
    gemm_tc<EPI_BIAS><<<gproj, 256>>>(Wv, x, bv, v, A_DIM, L_DIM, CIN_DIM, 0, XL, AL);

    // 2) Fused attention
    attn_stats<<<dim3(8, BH_DIM), 256, SMEM1>>>(q, k, mx, is);
    attn_out<<<dim3(8, BH_DIM), 512, SMEM2>>>(q, k, v, mx, is, h);

    // 3) Final MLP
    dim3 gf(L_DIM / 128, A_DIM / 128, B_DIM);
    gemm_tc<EPI_BIAS_RELU><<<gf, 256>>>(W1, h, b1, z, A_DIM, L_DIM, A_DIM, 0, AL, AL);
    gemm_tc<EPI_BIAS><<<gf, 256>>>(W2, z, b2, out, A_DIM, L_DIM, A_DIM, 0, AL, AL);
}

// round 7
// speedup vs baseline: 1.3852x; 1.3852x over previous
#include <cuda_runtime.h>
#include <cstdint>
#include <math.h>

#define B_DIM 2
#define CIN_DIM 512
#define L_DIM 1024
#define H_DIM 32
#define D_DIM 64
#define A_DIM 2048
#define BH_DIM (B_DIM * H_DIM)

// Scratch
__device__ float g_q[B_DIM * A_DIM * L_DIM];
__device__ float g_k[B_DIM * A_DIM * L_DIM];
__device__ float g_v[B_DIM * A_DIM * L_DIM];
__device__ float g_h[B_DIM * A_DIM * L_DIM];
__device__ float g_z[B_DIM * A_DIM * L_DIM];
__device__ float g_mx[BH_DIM * L_DIM];
__device__ float g_is[BH_DIM * L_DIM];
// tf32-pre-rounded operands
__device__ float g_wq[A_DIM * CIN_DIM];
__device__ float g_wk[A_DIM * CIN_DIM];
__device__ float g_wv[A_DIM * CIN_DIM];
__device__ float g_w1[A_DIM * A_DIM];
__device__ float g_w2[A_DIM * A_DIM];
__device__ float g_xr[B_DIM * CIN_DIM * L_DIM];

enum { EPI_NONE = 0, EPI_BIAS = 1, EPI_BIAS_RELU = 2, EPI_RELU = 3 };

__device__ __forceinline__ float cvt_tf32(float x) {
    uint32_t u;
    asm("cvt.rna.tf32.f32 %0, %1;" : "=r"(u) : "f"(x));
    return __uint_as_float(u);
}

__device__ __forceinline__ void mma_tf32(float c[4], const uint32_t a[4], const uint32_t b[2]) {
    asm volatile(
        "mma.sync.aligned.m16n8k8.row.col.f32.tf32.tf32.f32 "
        "{%0,%1,%2,%3}, {%4,%5,%6,%7}, {%8,%9}, {%0,%1,%2,%3};\n"
        : "+f"(c[0]), "+f"(c[1]), "+f"(c[2]), "+f"(c[3])
        : "r"(a[0]), "r"(a[1]), "r"(a[2]), "r"(a[3]), "r"(b[0]), "r"(b[1]));
}

__device__ __forceinline__ void cp_async16(float* sptr, const float* gptr) {
    uint32_t s = (uint32_t)__cvta_generic_to_shared(sptr);
    asm volatile("cp.async.cg.shared.global [%0], [%1], 16;\n" :: "r"(s), "l"(gptr));
}
__device__ __forceinline__ void cp_commit() { asm volatile("cp.async.commit_group;\n"); }
__device__ __forceinline__ void cp_wait0() { asm volatile("cp.async.wait_group 0;\n"); }
__device__ __forceinline__ void cp_wait1() { asm volatile("cp.async.wait_group 1;\n"); }

// ============================================================================
// Pre-round: dst[i] = tf32_rna(src[i]); n % 4 == 0
// ============================================================================
__global__ void round_copy(const float* __restrict__ src, float* __restrict__ dst, int n)
{
    int i = (blockIdx.x * blockDim.x + threadIdx.x) * 4;
    if (i < n) {
        float4 t = *(const float4*)&src[i];
        t.x = cvt_tf32(t.x); t.y = cvt_tf32(t.y);
        t.z = cvt_tf32(t.z); t.w = cvt_tf32(t.w);
        *(float4*)&dst[i] = t;
    }
}

// ============================================================================
// TF32 GEMM, cp.async 2-stage, zero in-loop conversions.
// Inputs MUST already be tf32-rounded. A row-major [M,K] stays [m][k] in smem
// (stride 36 -> conflict-free A-frag loads); B [K,N] -> [k][n] stride 136.
// Requires M%128==0, N%128==0, K%32==0.
// RND: round outputs to tf32 before store (for tensors consumed by later MMAs).
// ============================================================================
template <int EPI, bool RND>
__global__ __launch_bounds__(256, 2) void gemm_tc(
    const float* __restrict__ Ag, const float* __restrict__ Bg,
    const float* __restrict__ bias, float* __restrict__ Cg,
    int M, int N, int K,
    long long Abs, long long Bbs, long long Cbs)
{
    constexpr int BM = 128, BN = 128, KC = 32;
    constexpr int ASTR = KC + 4;     // 36: (r*36+c)%32 = 4r+c -> conflict-free
    constexpr int BSTR = BN + 8;     // 136
    constexpr int SS = BM * ASTR + KC * BSTR;   // floats per stage (8960)

    extern __shared__ float sm[];
    float* Asb[2] = { sm,            sm + SS };
    float* Bsb[2] = { sm + BM * ASTR, sm + SS + BM * ASTR };

    const float* Ap = Ag + (long long)blockIdx.z * Abs;
    const float* Bp = Bg + (long long)blockIdx.z * Bbs;
    float* Cp = Cg + (long long)blockIdx.z * Cbs;

    const int tid = threadIdx.x;
    const int lane = tid & 31;
    const int w = tid >> 5;
    const int wm = w & 3, wn = w >> 2;          // 4 x 2 warps
    const int row = lane >> 2, kq = lane & 3;
    const int row0 = blockIdx.y * BM;
    const int col0 = blockIdx.x * BN;

    auto issue = [&](int k0, int buf) {
        float* A_ = Asb[buf];
        float* B_ = Bsb[buf];
#pragma unroll
        for (int u = 0; u < 4; ++u) {           // A: 128 rows x 32 floats
            int idx = tid + u * 256;
            int r = idx >> 3, j = idx & 7;
            cp_async16(&A_[r * ASTR + 4 * j], &Ap[(long long)(row0 + r) * K + k0 + 4 * j]);
        }
#pragma unroll
        for (int u = 0; u < 4; ++u) {           // B: 32 rows x 128 floats
            int idx = tid + u * 256;
            int kk = idx >> 5, nq = idx & 31;
            cp_async16(&B_[kk * BSTR + 4 * nq], &Bp[(long long)(k0 + kk) * N + col0 + 4 * nq]);
        }
        cp_commit();
    };

    float acc[2][8][4] = {};

    issue(0, 0);
    const int nit = K / KC;
    for (int it = 0; it < nit; ++it) {
        int cur = it & 1;
        if (it + 1 < nit) issue((it + 1) * KC, cur ^ 1);
        if (it + 1 < nit) cp_wait1(); else cp_wait0();
        __syncthreads();

        const float* A_ = Asb[cur];
        const float* B_ = Bsb[cur];
#pragma unroll
        for (int ks = 0; ks < KC; ks += 8) {
            uint32_t af[2][4];
#pragma unroll
            for (int f = 0; f < 2; ++f) {
                const float* Ab = &A_[(wm * 32 + f * 16 + row) * ASTR + ks + kq];
                af[f][0] = __float_as_uint(Ab[0]);
                af[f][1] = __float_as_uint(Ab[8 * ASTR]);
                af[f][2] = __float_as_uint(Ab[4]);
                af[f][3] = __float_as_uint(Ab[8 * ASTR + 4]);
            }
            uint32_t bf[8][2];
#pragma unroll
            for (int g = 0; g < 8; ++g) {
                const float* Bb = &B_[(ks + kq) * BSTR + wn * 64 + g * 8 + row];
                bf[g][0] = __float_as_uint(Bb[0]);
                bf[g][1] = __float_as_uint(Bb[4 * BSTR]);
            }
#pragma unroll
            for (int f = 0; f < 2; ++f)
#pragma unroll
                for (int g = 0; g < 8; ++g)
                    mma_tf32(acc[f][g], af[f], bf[g]);
        }
        __syncthreads();   // reads of buf done before it is reissued
    }

#pragma unroll
    for (int f = 0; f < 2; ++f) {
        int r = row0 + wm * 32 + f * 16 + row;
        float b0v = 0.f, b8v = 0.f;
        if (EPI == EPI_BIAS || EPI == EPI_BIAS_RELU) { b0v = bias[r]; b8v = bias[r + 8]; }
#pragma unroll
        for (int g = 0; g < 8; ++g) {
            int c = col0 + wn * 64 + g * 8 + kq * 2;
            float v0 = acc[f][g][0] + b0v;
            float v1 = acc[f][g][1] + b0v;
            float v2 = acc[f][g][2] + b8v;
            float v3 = acc[f][g][3] + b8v;
            if (EPI == EPI_RELU || EPI == EPI_BIAS_RELU) {
                v0 = fmaxf(v0, 0.f); v1 = fmaxf(v1, 0.f);
                v2 = fmaxf(v2, 0.f); v3 = fmaxf(v3, 0.f);
            }
            if (RND) {
                v0 = cvt_tf32(v0); v1 = cvt_tf32(v1);
                v2 = cvt_tf32(v2); v3 = cvt_tf32(v3);
            }
            *(float2*)&Cp[(long long)r * N + c] = make_float2(v0, v1);
            *(float2*)&Cp[(long long)(r + 8) * N + c] = make_float2(v2, v3);
        }
    }
}

// ============================================================================
// Attention pass 1: softmax row stats. q,k are pre-rounded -> no cvts.
// ============================================================================
__global__ __launch_bounds__(256, 2) void attn_stats(
    const float* __restrict__ q, const float* __restrict__ k,
    float* __restrict__ gM, float* __restrict__ gIS)
{
    extern __shared__ float smem[];
    float* Qs = smem;                    // [64][136]
    float* Kb[2] = { smem + 64 * 136, smem + 2 * 64 * 136 };

    const long long DL = (long long)D_DIM * L_DIM;
    const int bh = blockIdx.y;
    const int l0 = blockIdx.x * 128;
    const float* qh = q + (long long)bh * DL;
    const float* kh = k + (long long)bh * DL;
    const int tid = threadIdx.x, lane = tid & 31, w = tid >> 5;
    const int wm = w & 3, wn = w >> 2;
    const int row = lane >> 2, kq = lane & 3;

#pragma unroll
    for (int u = 0; u < 8; ++u) {
        int idx = tid + u * 256;
        int d = idx >> 5, c = (idx & 31) * 4;
        cp_async16(&Kb[0][d * 136 + c], &kh[(long long)d * L_DIM + c]);
    }
    cp_commit();

#pragma unroll
    for (int u = 0; u < 8; ++u) {
        int idx = tid + u * 256;
        int d = idx >> 5, c = (idx & 31) * 4;
        *(float4*)&Qs[d * 136 + c] = *(const float4*)&qh[(long long)d * L_DIM + l0 + c];
    }

    float Mx[4] = { -1e30f, -1e30f, -1e30f, -1e30f };
    float Sm[4] = { 0.f, 0.f, 0.f, 0.f };

    for (int mt = 0; mt < 8; ++mt) {
        const float* Ks = Kb[mt & 1];
        cp_wait0();
        __syncthreads();
        if (mt < 7) {
            float* Kn = Kb[(mt & 1) ^ 1];
#pragma unroll
            for (int u = 0; u < 8; ++u) {
                int idx = tid + u * 256;
                int d = idx >> 5, c = (idx & 31) * 4;
                cp_async16(&Kn[d * 136 + c], &kh[(long long)d * L_DIM + (mt + 1) * 128 + c]);
            }
            cp_commit();
        }

        float acc[2][8][4] = {};
#pragma unroll
        for (int ks = 0; ks < 64; ks += 8) {
            uint32_t af[2][4];
#pragma unroll
            for (int f = 0; f < 2; ++f) {
                const float* Ab = &Qs[(ks + kq) * 136 + wm * 32 + f * 16 + row];
                af[f][0] = __float_as_uint(Ab[0]);
                af[f][1] = __float_as_uint(Ab[8]);
                af[f][2] = __float_as_uint(Ab[4 * 136]);
                af[f][3] = __float_as_uint(Ab[4 * 136 + 8]);
            }
            uint32_t bf[8][2];
#pragma unroll
            for (int g = 0; g < 8; ++g) {
                const float* Bb = &Ks[(ks + kq) * 136 + wn * 64 + g * 8 + row];
                bf[g][0] = __float_as_uint(Bb[0]);
                bf[g][1] = __float_as_uint(Bb[4 * 136]);
            }
#pragma unroll
            for (int f = 0; f < 2; ++f)
#pragma unroll
                for (int g = 0; g < 8; ++g)
                    mma_tf32(acc[f][g], af[f], bf[g]);
        }

#pragma unroll
        for (int f = 0; f < 2; ++f)
#pragma unroll
            for (int sub = 0; sub < 2; ++sub) {
                int lr = l0 + wm * 32 + f * 16 + sub * 8 + row;
                float tm = -1e30f;
#pragma unroll
                for (int g = 0; g < 8; ++g) {
                    int m = mt * 128 + wn * 64 + g * 8 + kq * 2;
                    float x0 = (acc[f][g][2 * sub]     - fabsf((float)(lr - m)))     * 0.125f;
                    float x1 = (acc[f][g][2 * sub + 1] - fabsf((float)(lr - m - 1))) * 0.125f;
                    tm = fmaxf(tm, fmaxf(x0, x1));
                }
                float ts = 0.f;
#pragma unroll
                for (int g = 0; g < 8; ++g) {
                    int m = mt * 128 + wn * 64 + g * 8 + kq * 2;
                    float x0 = (acc[f][g][2 * sub]     - fabsf((float)(lr - m)))     * 0.125f;
                    float x1 = (acc[f][g][2 * sub + 1] - fabsf((float)(lr - m - 1))) * 0.125f;
                    ts += __expf(x0 - tm) + __expf(x1 - tm);
                }
                int i = 2 * f + sub;
                float nm = fmaxf(Mx[i], tm);
                Sm[i] = Sm[i] * __expf(Mx[i] - nm) + ts * __expf(tm - nm);
                Mx[i] = nm;
            }
    }

#pragma unroll
    for (int i = 0; i < 4; ++i) {
#pragma unroll
        for (int o = 1; o <= 2; o <<= 1) {
            float oM = __shfl_xor_sync(0xffffffffu, Mx[i], o);
            float oS = __shfl_xor_sync(0xffffffffu, Sm[i], o);
            float nm = fmaxf(Mx[i], oM);
            Sm[i] = Sm[i] * __expf(Mx[i] - nm) + oS * __expf(oM - nm);
            Mx[i] = nm;
        }
    }
    __syncthreads();
    float* sM = Qs;
    float* sS = Qs + 256;
    if (kq == 0) {
#pragma unroll
        for (int f = 0; f < 2; ++f)
#pragma unroll
            for (int sub = 0; sub < 2; ++sub) {
                int rl = wm * 32 + f * 16 + sub * 8 + row;
                sM[wn * 128 + rl] = Mx[2 * f + sub];
                sS[wn * 128 + rl] = Sm[2 * f + sub];
            }
    }
    __syncthreads();
    if (tid < 128) {
        float M0 = sM[tid], M1 = sM[128 + tid];
        float S0 = sS[tid], S1 = sS[128 + tid];
        float nm = fmaxf(M0, M1);
        float S = S0 * __expf(M0 - nm) + S1 * __expf(M1 - nm);
        gM[bh * L_DIM + l0 + tid] = nm;
        gIS[bh * L_DIM + l0 + tid] = 1.0f / S;
    }
}

// ============================================================================
// Attention pass 2 (512 threads): O^T[m,d] = W^T @ V. q,k,v pre-rounded.
// h output stored tf32-rounded (consumed by MLP1's MMA).
// ============================================================================
__global__ __launch_bounds__(512) void attn_out(
    const float* __restrict__ q, const float* __restrict__ k,
    const float* __restrict__ v, const float* __restrict__ gM,
    const float* __restrict__ gIS, float* __restrict__ hout)
{
    extern __shared__ float smem[];
    float* Qs = smem;                       // [d=64][l=128] str 136
    float* Vs = Qs + 64 * 136;              // [d=64][l=128] str 132
    float* Ks = Vs + 64 * 132;              // [d=64][m=128] str 136
    float* Ws = Ks + 64 * 136;              // [l=128][m=128] str 136

    const long long DL = (long long)D_DIM * L_DIM;
    const int bh = blockIdx.y;
    const int mb = (int)(gridDim.x - 1 - blockIdx.x);
    const int m0 = mb * 128;
    const float* qh = q + (long long)bh * DL;
    const float* kh = k + (long long)bh * DL;
    const float* vh = v + (long long)bh * DL;
    const int tid = threadIdx.x, lane = tid & 31, w = tid >> 5;
    const int wm = w & 3, wn = w >> 2;
    const int row = lane >> 2, kq = lane & 3;

    auto issueQ = [&](int lb) {
#pragma unroll
        for (int u = 0; u < 4; ++u) {
            int idx = tid + u * 512;
            int d = idx >> 5, c = (idx & 31) * 4;
            cp_async16(&Qs[d * 136 + c], &qh[(long long)d * L_DIM + lb * 128 + c]);
        }
        cp_commit();
    };
    auto issueV = [&](int lb) {
#pragma unroll
        for (int u = 0; u < 4; ++u) {
            int idx = tid + u * 512;
            int d = idx >> 5, c = (idx & 31) * 4;
            cp_async16(&Vs[d * 132 + c], &vh[(long long)d * L_DIM + lb * 128 + c]);
        }
        cp_commit();
    };

    issueQ(0);

#pragma unroll
    for (int u = 0; u < 4; ++u) {
        int idx = tid + u * 512;
        int d = idx >> 5, c = (idx & 31) * 4;
        *(float4*)&Ks[d * 136 + c] = *(const float4*)&kh[(long long)d * L_DIM + m0 + c];
    }

    float accO[2][2][4] = {};

    for (int lb = 0; lb <= mb; ++lb) {
        cp_wait0();
        __syncthreads();
        issueV(lb);

        float acc[2][4][4] = {};
#pragma unroll
        for (int ks = 0; ks < 64; ks += 8) {
            uint32_t af[2][4];
#pragma unroll
            for (int f = 0; f < 2; ++f) {
                const float* Ab = &Qs[(ks + kq) * 136 + wm * 32 + f * 16 + row];
                af[f][0] = __float_as_uint(Ab[0]);
                af[f][1] = __float_as_uint(Ab[8]);
                af[f][2] = __float_as_uint(Ab[4 * 136]);
                af[f][3] = __float_as_uint(Ab[4 * 136 + 8]);
            }
            uint32_t bf[4][2];
#pragma unroll
            for (int g = 0; g < 4; ++g) {
                const float* Bb = &Ks[(ks + kq) * 136 + wn * 32 + g * 8 + row];
                bf[g][0] = __float_as_uint(Bb[0]);
                bf[g][1] = __float_as_uint(Bb[4 * 136]);
            }
#pragma unroll
            for (int f = 0; f < 2; ++f)
#pragma unroll
                for (int g = 0; g < 4; ++g)
                    mma_tf32(acc[f][g], af[f], bf[g]);
        }

#pragma unroll
        for (int f = 0; f < 2; ++f)
#pragma unroll
            for (int sub = 0; sub < 2; ++sub) {
                int lloc = wm * 32 + f * 16 + sub * 8 + row;
                int lg = lb * 128 + lloc;
                float Mrow = gM[bh * L_DIM + lg];
                float IS = gIS[bh * L_DIM + lg];
#pragma unroll
                for (int g = 0; g < 4; ++g) {
                    int c = wn * 32 + g * 8 + kq * 2;
                    int mg = m0 + c;
                    float x0 = (acc[f][g][2 * sub]     - fabsf((float)(lg - mg)))     * 0.125f;
                    float x1 = (acc[f][g][2 * sub + 1] - fabsf((float)(lg - mg - 1))) * 0.125f;
                    float w0 = __expf(x0 - Mrow) * IS;
                    float w1 = __expf(x1 - Mrow) * IS;
                    if (lb == mb) {
                        if (lg > mg)     w0 = 0.f;
                        if (lg > mg + 1) w1 = 0.f;
                    }
                    float2 t2;
                    t2.x = cvt_tf32(w0);
                    t2.y = cvt_tf32(w1);
                    *(float2*)&Ws[lloc * 136 + c] = t2;
                }
            }
        __syncthreads();
        if (lb < mb) { issueQ(lb + 1); cp_wait1(); }
        else         { cp_wait0(); }
        __syncthreads();

#pragma unroll
        for (int ks = 0; ks < 128; ks += 8) {
            uint32_t af[2][4];
#pragma unroll
            for (int f = 0; f < 2; ++f) {
                const float* Ab = &Ws[(ks + kq) * 136 + wm * 32 + f * 16 + row];
                af[f][0] = __float_as_uint(Ab[0]);
                af[f][1] = __float_as_uint(Ab[8]);
                af[f][2] = __float_as_uint(Ab[4 * 136]);
                af[f][3] = __float_as_uint(Ab[4 * 136 + 8]);
            }
            uint32_t bf[2][2];
#pragma unroll
            for (int g = 0; g < 2; ++g) {
                const float* Bb = &Vs[(wn * 16 + g * 8 + row) * 132 + ks + kq];
                bf[g][0] = __float_as_uint(Bb[0]);
                bf[g][1] = __float_as_uint(Bb[4]);
            }
#pragma unroll
            for (int f = 0; f < 2; ++f)
#pragma unroll
                for (int g = 0; g < 2; ++g)
                    mma_tf32(accO[f][g], af[f], bf[g]);
        }
    }

    // epilogue: ReLU + tf32-round, transpose-store h[d][m]
#pragma unroll
    for (int f = 0; f < 2; ++f) {
        int rm = m0 + wm * 32 + f * 16 + row;
#pragma unroll
        for (int g = 0; g < 2; ++g) {
            int cd = wn * 16 + g * 8 + kq * 2;
            hout[(long long)bh * DL + (long long)cd * L_DIM + rm]           = cvt_tf32(fmaxf(accO[f][g][0], 0.f));
            hout[(long long)bh * DL + (long long)(cd + 1) * L_DIM + rm]     = cvt_tf32(fmaxf(accO[f][g][1], 0.f));
            hout[(long long)bh * DL + (long long)cd * L_DIM + rm + 8]       = cvt_tf32(fmaxf(accO[f][g][2], 0.f));
            hout[(long long)bh * DL + (long long)(cd + 1) * L_DIM + rm + 8] = cvt_tf32(fmaxf(accO[f][g][3], 0.f));
        }
    }
}

// ============================================================================
extern "C" void kernel_launch(void* const* d_in, const int* in_sizes, int n_in,
                              void* d_out, int out_size)
{
    (void)in_sizes; (void)n_in; (void)out_size;
    const float* x  = (const float*)d_in[0];
    const float* Wq = (const float*)d_in[1];
    const float* bq = (const float*)d_in[2];
    const float* Wk = (const float*)d_in[3];
    const float* bk = (const float*)d_in[4];
    const float* Wv = (const float*)d_in[5];
    const float* bv = (const float*)d_in[6];
    const float* W1 = (const float*)d_in[7];
    const float* b1 = (const float*)d_in[8];
    const float* W2 = (const float*)d_in[9];
    const float* b2 = (const float*)d_in[10];
    float* out = (float*)d_out;

    float *q, *k, *v, *h, *z, *mx, *is;
    float *wq, *wk, *wv, *w1, *w2, *xr;
    cudaGetSymbolAddress((void**)&q, g_q);
    cudaGetSymbolAddress((void**)&k, g_k);
    cudaGetSymbolAddress((void**)&v, g_v);
    cudaGetSymbolAddress((void**)&h, g_h);
    cudaGetSymbolAddress((void**)&z, g_z);
    cudaGetSymbolAddress((void**)&mx, g_mx);
    cudaGetSymbolAddress((void**)&is, g_is);
    cudaGetSymbolAddress((void**)&wq, g_wq);
    cudaGetSymbolAddress((void**)&wk, g_wk);
    cudaGetSymbolAddress((void**)&wv, g_wv);
    cudaGetSymbolAddress((void**)&w1, g_w1);
    cudaGetSymbolAddress((void**)&w2, g_w2);
    cudaGetSymbolAddress((void**)&xr, g_xr);

    const long long AL = (long long)A_DIM * L_DIM;
    const long long XL = (long long)CIN_DIM * L_DIM;

    const int SMEMG = 2 * (128 * 36 + 32 * 136) * 4;                     // 71680 B
    const int SMEM1 = (64 * 136 * 3) * 4;                                // 104448 B
    const int SMEM2 = (64 * 136 + 64 * 132 + 64 * 136 + 128 * 136) * 4;  // 173056 B
    cudaFuncSetAttribute(gemm_tc<EPI_BIAS, true>,       cudaFuncAttributeMaxDynamicSharedMemorySize, SMEMG);
    cudaFuncSetAttribute(gemm_tc<EPI_BIAS_RELU, true>,  cudaFuncAttributeMaxDynamicSharedMemorySize, SMEMG);
    cudaFuncSetAttribute(gemm_tc<EPI_BIAS, false>,      cudaFuncAttributeMaxDynamicSharedMemorySize, SMEMG);
    cudaFuncSetAttribute(attn_stats, cudaFuncAttributeMaxDynamicSharedMemorySize, SMEM1);
    cudaFuncSetAttribute(attn_out,   cudaFuncAttributeMaxDynamicSharedMemorySize, SMEM2);

    // 0) Pre-round all GEMM input operands to tf32 (RNA) once.
    const int WPROJ = A_DIM * CIN_DIM;       // 1M
    const int WMLP  = A_DIM * A_DIM;         // 4M
    const int XN    = B_DIM * CIN_DIM * L_DIM;
    round_copy<<<WPROJ / 1024, 256>>>(Wq, wq, WPROJ);
    round_copy<<<WPROJ / 1024, 256>>>(Wk, wk, WPROJ);
    round_copy<<<WPROJ / 1024, 256>>>(Wv, wv, WPROJ);
    round_copy<<<WMLP / 1024, 256>>>(W1, w1, WMLP);
    round_copy<<<WMLP / 1024, 256>>>(W2, w2, WMLP);
    round_copy<<<XN / 1024, 256>>>(x, xr, XN);

    // 1) QKV projections (outputs tf32-rounded)
    dim3 gproj(L_DIM / 128, A_DIM / 128, B_DIM);
    gemm_tc<EPI_BIAS, true><<<gproj, 256, SMEMG>>>(wq, xr, bq, q, A_DIM, L_DIM, CIN_DIM, 0, XL, AL);
    gemm_tc<EPI_BIAS, true><<<gproj, 256, SMEMG>>>(wk, xr, bk, k, A_DIM, L_DIM, CIN_DIM, 0, XL, AL);
    gemm_tc<EPI_BIAS, true><<<gproj, 256, SMEMG>>>(wv, xr, bv, v, A_DIM, L_DIM, CIN_DIM, 0, XL, AL);

    // 2) Fused attention
    attn_stats<<<dim3(8, BH_DIM), 256, SMEM1>>>(q, k, mx, is);
    attn_out<<<dim3(8, BH_DIM), 512, SMEM2>>>(q, k, v, mx, is, h);

    // 3) Final MLP (z rounded; final out NOT rounded)
    dim3 gf(L_DIM / 128, A_DIM / 128, B_DIM);
    gemm_tc<EPI_BIAS_RELU, true><<<gf, 256, SMEMG>>>(w1, h, b1, z, A_DIM, L_DIM, A_DIM, 0, AL, AL);
    gemm_tc<EPI_BIAS, false><<<gf, 256, SMEMG>>>(w2, z, b2, out, A_DIM, L_DIM, A_DIM, 0, AL, AL);
}

// round 8
// speedup vs baseline: 1.5721x; 1.1349x over previous
#include <cuda_runtime.h>
#include <cstdint>
#include <math.h>

#define B_DIM 2
#define CIN_DIM 512
#define L_DIM 1024
#define H_DIM 32
#define D_DIM 64
#define A_DIM 2048
#define BH_DIM (B_DIM * H_DIM)
#define BAND 2   // tile radius: contributions beyond 256 rows are < e^-17 of row max

// Scratch
__device__ float g_q[B_DIM * A_DIM * L_DIM];
__device__ float g_k[B_DIM * A_DIM * L_DIM];
__device__ float g_v[B_DIM * A_DIM * L_DIM];
__device__ float g_h[B_DIM * A_DIM * L_DIM];
__device__ float g_z[B_DIM * A_DIM * L_DIM];
__device__ float g_mx[BH_DIM * L_DIM];
__device__ float g_is[BH_DIM * L_DIM];
// tf32-pre-rounded operands
__device__ float g_wq[A_DIM * CIN_DIM];
__device__ float g_wk[A_DIM * CIN_DIM];
__device__ float g_wv[A_DIM * CIN_DIM];
__device__ float g_w1[A_DIM * A_DIM];
__device__ float g_w2[A_DIM * A_DIM];
__device__ float g_xr[B_DIM * CIN_DIM * L_DIM];

enum { EPI_NONE = 0, EPI_BIAS = 1, EPI_BIAS_RELU = 2, EPI_RELU = 3 };

__device__ __forceinline__ float cvt_tf32(float x) {
    uint32_t u;
    asm("cvt.rna.tf32.f32 %0, %1;" : "=r"(u) : "f"(x));
    return __uint_as_float(u);
}

__device__ __forceinline__ void mma_tf32(float c[4], const uint32_t a[4], const uint32_t b[2]) {
    asm volatile(
        "mma.sync.aligned.m16n8k8.row.col.f32.tf32.tf32.f32 "
        "{%0,%1,%2,%3}, {%4,%5,%6,%7}, {%8,%9}, {%0,%1,%2,%3};\n"
        : "+f"(c[0]), "+f"(c[1]), "+f"(c[2]), "+f"(c[3])
        : "r"(a[0]), "r"(a[1]), "r"(a[2]), "r"(a[3]), "r"(b[0]), "r"(b[1]));
}

__device__ __forceinline__ void cp_async16(float* sptr, const float* gptr) {
    uint32_t s = (uint32_t)__cvta_generic_to_shared(sptr);
    asm volatile("cp.async.cg.shared.global [%0], [%1], 16;\n" :: "r"(s), "l"(gptr));
}
__device__ __forceinline__ void cp_commit() { asm volatile("cp.async.commit_group;\n"); }
__device__ __forceinline__ void cp_wait0() { asm volatile("cp.async.wait_group 0;\n"); }
__device__ __forceinline__ void cp_wait1() { asm volatile("cp.async.wait_group 1;\n"); }

// ============================================================================
__global__ void round_copy(const float* __restrict__ src, float* __restrict__ dst, int n)
{
    int i = (blockIdx.x * blockDim.x + threadIdx.x) * 4;
    if (i < n) {
        float4 t = *(const float4*)&src[i];
        t.x = cvt_tf32(t.x); t.y = cvt_tf32(t.y);
        t.z = cvt_tf32(t.z); t.w = cvt_tf32(t.w);
        *(float4*)&dst[i] = t;
    }
}

// ============================================================================
// TF32 GEMM, cp.async 2-stage, zero in-loop conversions (round-7, unchanged).
// ============================================================================
template <int EPI, bool RND>
__global__ __launch_bounds__(256, 2) void gemm_tc(
    const float* __restrict__ Ag, const float* __restrict__ Bg,
    const float* __restrict__ bias, float* __restrict__ Cg,
    int M, int N, int K,
    long long Abs, long long Bbs, long long Cbs)
{
    constexpr int BM = 128, BN = 128, KC = 32;
    constexpr int ASTR = KC + 4;
    constexpr int BSTR = BN + 8;
    constexpr int SS = BM * ASTR + KC * BSTR;

    extern __shared__ float sm[];
    float* Asb[2] = { sm,             sm + SS };
    float* Bsb[2] = { sm + BM * ASTR, sm + SS + BM * ASTR };

    const float* Ap = Ag + (long long)blockIdx.z * Abs;
    const float* Bp = Bg + (long long)blockIdx.z * Bbs;
    float* Cp = Cg + (long long)blockIdx.z * Cbs;

    const int tid = threadIdx.x;
    const int lane = tid & 31;
    const int w = tid >> 5;
    const int wm = w & 3, wn = w >> 2;
    const int row = lane >> 2, kq = lane & 3;
    const int row0 = blockIdx.y * BM;
    const int col0 = blockIdx.x * BN;

    auto issue = [&](int k0, int buf) {
        float* A_ = Asb[buf];
        float* B_ = Bsb[buf];
#pragma unroll
        for (int u = 0; u < 4; ++u) {
            int idx = tid + u * 256;
            int r = idx >> 3, j = idx & 7;
            cp_async16(&A_[r * ASTR + 4 * j], &Ap[(long long)(row0 + r) * K + k0 + 4 * j]);
        }
#pragma unroll
        for (int u = 0; u < 4; ++u) {
            int idx = tid + u * 256;
            int kk = idx >> 5, nq = idx & 31;
            cp_async16(&B_[kk * BSTR + 4 * nq], &Bp[(long long)(k0 + kk) * N + col0 + 4 * nq]);
        }
        cp_commit();
    };

    float acc[2][8][4] = {};

    issue(0, 0);
    const int nit = K / KC;
    for (int it = 0; it < nit; ++it) {
        int cur = it & 1;
        if (it + 1 < nit) issue((it + 1) * KC, cur ^ 1);
        if (it + 1 < nit) cp_wait1(); else cp_wait0();
        __syncthreads();

        const float* A_ = Asb[cur];
        const float* B_ = Bsb[cur];
#pragma unroll
        for (int ks = 0; ks < KC; ks += 8) {
            uint32_t af[2][4];
#pragma unroll
            for (int f = 0; f < 2; ++f) {
                const float* Ab = &A_[(wm * 32 + f * 16 + row) * ASTR + ks + kq];
                af[f][0] = __float_as_uint(Ab[0]);
                af[f][1] = __float_as_uint(Ab[8 * ASTR]);
                af[f][2] = __float_as_uint(Ab[4]);
                af[f][3] = __float_as_uint(Ab[8 * ASTR + 4]);
            }
            uint32_t bf[8][2];
#pragma unroll
            for (int g = 0; g < 8; ++g) {
                const float* Bb = &B_[(ks + kq) * BSTR + wn * 64 + g * 8 + row];
                bf[g][0] = __float_as_uint(Bb[0]);
                bf[g][1] = __float_as_uint(Bb[4 * BSTR]);
            }
#pragma unroll
            for (int f = 0; f < 2; ++f)
#pragma unroll
                for (int g = 0; g < 8; ++g)
                    mma_tf32(acc[f][g], af[f], bf[g]);
        }
        __syncthreads();
    }

#pragma unroll
    for (int f = 0; f < 2; ++f) {
        int r = row0 + wm * 32 + f * 16 + row;
        float b0v = 0.f, b8v = 0.f;
        if (EPI == EPI_BIAS || EPI == EPI_BIAS_RELU) { b0v = bias[r]; b8v = bias[r + 8]; }
#pragma unroll
        for (int g = 0; g < 8; ++g) {
            int c = col0 + wn * 64 + g * 8 + kq * 2;
            float v0 = acc[f][g][0] + b0v;
            float v1 = acc[f][g][1] + b0v;
            float v2 = acc[f][g][2] + b8v;
            float v3 = acc[f][g][3] + b8v;
            if (EPI == EPI_RELU || EPI == EPI_BIAS_RELU) {
                v0 = fmaxf(v0, 0.f); v1 = fmaxf(v1, 0.f);
                v2 = fmaxf(v2, 0.f); v3 = fmaxf(v3, 0.f);
            }
            if (RND) {
                v0 = cvt_tf32(v0); v1 = cvt_tf32(v1);
                v2 = cvt_tf32(v2); v3 = cvt_tf32(v3);
            }
            *(float2*)&Cp[(long long)r * N + c] = make_float2(v0, v1);
            *(float2*)&Cp[(long long)(r + 8) * N + c] = make_float2(v2, v3);
        }
    }
}

// ============================================================================
// Attention pass 1 (BANDED): softmax row stats over m-tiles |mt - lt| <= BAND.
// Omitted tiles contribute < e^-17 of the row max — below fp32 softmax noise.
// ============================================================================
__global__ __launch_bounds__(256, 2) void attn_stats(
    const float* __restrict__ q, const float* __restrict__ k,
    float* __restrict__ gM, float* __restrict__ gIS)
{
    extern __shared__ float smem[];
    float* Qs = smem;                    // [64][136]
    float* Kb[2] = { smem + 64 * 136, smem + 2 * 64 * 136 };

    const long long DL = (long long)D_DIM * L_DIM;
    const int bh = blockIdx.y;
    const int lt = blockIdx.x;
    const int l0 = lt * 128;
    const int mt_lo = (lt - BAND > 0) ? lt - BAND : 0;
    const int mt_hi = (lt + BAND < 7) ? lt + BAND : 7;
    const float* qh = q + (long long)bh * DL;
    const float* kh = k + (long long)bh * DL;
    const int tid = threadIdx.x, lane = tid & 31, w = tid >> 5;
    const int wm = w & 3, wn = w >> 2;
    const int row = lane >> 2, kq = lane & 3;

    // prefetch K(mt_lo)
#pragma unroll
    for (int u = 0; u < 8; ++u) {
        int idx = tid + u * 256;
        int d = idx >> 5, c = (idx & 31) * 4;
        cp_async16(&Kb[mt_lo & 1][d * 136 + c], &kh[(long long)d * L_DIM + mt_lo * 128 + c]);
    }
    cp_commit();

#pragma unroll
    for (int u = 0; u < 8; ++u) {
        int idx = tid + u * 256;
        int d = idx >> 5, c = (idx & 31) * 4;
        *(float4*)&Qs[d * 136 + c] = *(const float4*)&qh[(long long)d * L_DIM + l0 + c];
    }

    float Mx[4] = { -1e30f, -1e30f, -1e30f, -1e30f };
    float Sm[4] = { 0.f, 0.f, 0.f, 0.f };

    for (int mt = mt_lo; mt <= mt_hi; ++mt) {
        const float* Ks = Kb[mt & 1];
        cp_wait0();
        __syncthreads();
        if (mt < mt_hi) {
            float* Kn = Kb[(mt & 1) ^ 1];
#pragma unroll
            for (int u = 0; u < 8; ++u) {
                int idx = tid + u * 256;
                int d = idx >> 5, c = (idx & 31) * 4;
                cp_async16(&Kn[d * 136 + c], &kh[(long long)d * L_DIM + (mt + 1) * 128 + c]);
            }
            cp_commit();
        }

        float acc[2][8][4] = {};
#pragma unroll
        for (int ks = 0; ks < 64; ks += 8) {
            uint32_t af[2][4];
#pragma unroll
            for (int f = 0; f < 2; ++f) {
                const float* Ab = &Qs[(ks + kq) * 136 + wm * 32 + f * 16 + row];
                af[f][0] = __float_as_uint(Ab[0]);
                af[f][1] = __float_as_uint(Ab[8]);
                af[f][2] = __float_as_uint(Ab[4 * 136]);
                af[f][3] = __float_as_uint(Ab[4 * 136 + 8]);
            }
            uint32_t bf[8][2];
#pragma unroll
            for (int g = 0; g < 8; ++g) {
                const float* Bb = &Ks[(ks + kq) * 136 + wn * 64 + g * 8 + row];
                bf[g][0] = __float_as_uint(Bb[0]);
                bf[g][1] = __float_as_uint(Bb[4 * 136]);
            }
#pragma unroll
            for (int f = 0; f < 2; ++f)
#pragma unroll
                for (int g = 0; g < 8; ++g)
                    mma_tf32(acc[f][g], af[f], bf[g]);
        }

#pragma unroll
        for (int f = 0; f < 2; ++f)
#pragma unroll
            for (int sub = 0; sub < 2; ++sub) {
                int lr = l0 + wm * 32 + f * 16 + sub * 8 + row;
                float tm = -1e30f;
#pragma unroll
                for (int g = 0; g < 8; ++g) {
                    int m = mt * 128 + wn * 64 + g * 8 + kq * 2;
                    float x0 = (acc[f][g][2 * sub]     - fabsf((float)(lr - m)))     * 0.125f;
                    float x1 = (acc[f][g][2 * sub + 1] - fabsf((float)(lr - m - 1))) * 0.125f;
                    tm = fmaxf(tm, fmaxf(x0, x1));
                }
                float ts = 0.f;
#pragma unroll
                for (int g = 0; g < 8; ++g) {
                    int m = mt * 128 + wn * 64 + g * 8 + kq * 2;
                    float x0 = (acc[f][g][2 * sub]     - fabsf((float)(lr - m)))     * 0.125f;
                    float x1 = (acc[f][g][2 * sub + 1] - fabsf((float)(lr - m - 1))) * 0.125f;
                    ts += __expf(x0 - tm) + __expf(x1 - tm);
                }
                int i = 2 * f + sub;
                float nm = fmaxf(Mx[i], tm);
                Sm[i] = Sm[i] * __expf(Mx[i] - nm) + ts * __expf(tm - nm);
                Mx[i] = nm;
            }
    }

#pragma unroll
    for (int i = 0; i < 4; ++i) {
#pragma unroll
        for (int o = 1; o <= 2; o <<= 1) {
            float oM = __shfl_xor_sync(0xffffffffu, Mx[i], o);
            float oS = __shfl_xor_sync(0xffffffffu, Sm[i], o);
            float nm = fmaxf(Mx[i], oM);
            Sm[i] = Sm[i] * __expf(Mx[i] - nm) + oS * __expf(oM - nm);
            Mx[i] = nm;
        }
    }
    __syncthreads();
    float* sM = Qs;
    float* sS = Qs + 256;
    if (kq == 0) {
#pragma unroll
        for (int f = 0; f < 2; ++f)
#pragma unroll
            for (int sub = 0; sub < 2; ++sub) {
                int rl = wm * 32 + f * 16 + sub * 8 + row;
                sM[wn * 128 + rl] = Mx[2 * f + sub];
                sS[wn * 128 + rl] = Sm[2 * f + sub];
            }
    }
    __syncthreads();
    if (tid < 128) {
        float M0 = sM[tid], M1 = sM[128 + tid];
        float S0 = sS[tid], S1 = sS[128 + tid];
        float nm = fmaxf(M0, M1);
        float S = S0 * __expf(M0 - nm) + S1 * __expf(M1 - nm);
        gM[bh * L_DIM + l0 + tid] = nm;
        gIS[bh * L_DIM + l0 + tid] = 1.0f / S;
    }
}

// ============================================================================
// Attention pass 2 (BANDED, 512 threads): O^T[m,d] = W^T @ V over
// lb in [max(0, mb-BAND), mb]; lower tiles have weight < e^-17 of row max.
// ============================================================================
__global__ __launch_bounds__(512) void attn_out(
    const float* __restrict__ q, const float* __restrict__ k,
    const float* __restrict__ v, const float* __restrict__ gM,
    const float* __restrict__ gIS, float* __restrict__ hout)
{
    extern __shared__ float smem[];
    float* Qs = smem;                       // [d=64][l=128] str 136
    float* Vs = Qs + 64 * 136;              // [d=64][l=128] str 132
    float* Ks = Vs + 64 * 132;              // [d=64][m=128] str 136
    float* Ws = Ks + 64 * 136;              // [l=128][m=128] str 136

    const long long DL = (long long)D_DIM * L_DIM;
    const int bh = blockIdx.y;
    const int mb = (int)(gridDim.x - 1 - blockIdx.x);
    const int m0 = mb * 128;
    const int lb0 = (mb - BAND > 0) ? mb - BAND : 0;
    const float* qh = q + (long long)bh * DL;
    const float* kh = k + (long long)bh * DL;
    const float* vh = v + (long long)bh * DL;
    const int tid = threadIdx.x, lane = tid & 31, w = tid >> 5;
    const int wm = w & 3, wn = w >> 2;
    const int row = lane >> 2, kq = lane & 3;

    auto issueQ = [&](int lb) {
#pragma unroll
        for (int u = 0; u < 4; ++u) {
            int idx = tid + u * 512;
            int d = idx >> 5, c = (idx & 31) * 4;
            cp_async16(&Qs[d * 136 + c], &qh[(long long)d * L_DIM + lb * 128 + c]);
        }
        cp_commit();
    };
    auto issueV = [&](int lb) {
#pragma unroll
        for (int u = 0; u < 4; ++u) {
            int idx = tid + u * 512;
            int d = idx >> 5, c = (idx & 31) * 4;
            cp_async16(&Vs[d * 132 + c], &vh[(long long)d * L_DIM + lb * 128 + c]);
        }
        cp_commit();
    };

    issueQ(lb0);

#pragma unroll
    for (int u = 0; u < 4; ++u) {
        int idx = tid + u * 512;
        int d = idx >> 5, c = (idx & 31) * 4;
        *(float4*)&Ks[d * 136 + c] = *(const float4*)&kh[(long long)d * L_DIM + m0 + c];
    }

    float accO[2][2][4] = {};

    for (int lb = lb0; lb <= mb; ++lb) {
        cp_wait0();
        __syncthreads();
        issueV(lb);

        float acc[2][4][4] = {};
#pragma unroll
        for (int ks = 0; ks < 64; ks += 8) {
            uint32_t af[2][4];
#pragma unroll
            for (int f = 0; f < 2; ++f) {
                const float* Ab = &Qs[(ks + kq) * 136 + wm * 32 + f * 16 + row];
                af[f][0] = __float_as_uint(Ab[0]);
                af[f][1] = __float_as_uint(Ab[8]);
                af[f][2] = __float_as_uint(Ab[4 * 136]);
                af[f][3] = __float_as_uint(Ab[4 * 136 + 8]);
            }
            uint32_t bf[4][2];
#pragma unroll
            for (int g = 0; g < 4; ++g) {
                const float* Bb = &Ks[(ks + kq) * 136 + wn * 32 + g * 8 + row];
                bf[g][0] = __float_as_uint(Bb[0]);
                bf[g][1] = __float_as_uint(Bb[4 * 136]);
            }
#pragma unroll
            for (int f = 0; f < 2; ++f)
#pragma unroll
                for (int g = 0; g < 4; ++g)
                    mma_tf32(acc[f][g], af[f], bf[g]);
        }

#pragma unroll
        for (int f = 0; f < 2; ++f)
#pragma unroll
            for (int sub = 0; sub < 2; ++sub) {
                int lloc = wm * 32 + f * 16 + sub * 8 + row;
                int lg = lb * 128 + lloc;
                float Mrow = gM[bh * L_DIM + lg];
                float IS = gIS[bh * L_DIM + lg];
#pragma unroll
                for (int g = 0; g < 4; ++g) {
                    int c = wn * 32 + g * 8 + kq * 2;
                    int mg = m0 + c;
                    float x0 = (acc[f][g][2 * sub]     - fabsf((float)(lg - mg)))     * 0.125f;
                    float x1 = (acc[f][g][2 * sub + 1] - fabsf((float)(lg - mg - 1))) * 0.125f;
                    float w0 = __expf(x0 - Mrow) * IS;
                    float w1 = __expf(x1 - Mrow) * IS;
                    if (lb == mb) {
                        if (lg > mg)     w0 = 0.f;
                        if (lg > mg + 1) w1 = 0.f;
                    }
                    float2 t2;
                    t2.x = cvt_tf32(w0);
                    t2.y = cvt_tf32(w1);
                    *(float2*)&Ws[lloc * 136 + c] = t2;
                }
            }
        __syncthreads();
        if (lb < mb) { issueQ(lb + 1); cp_wait1(); }
        else         { cp_wait0(); }
        __syncthreads();

#pragma unroll
        for (int ks = 0; ks < 128; ks += 8) {
            uint32_t af[2][4];
#pragma unroll
            for (int f = 0; f < 2; ++f) {
                const float* Ab = &Ws[(ks + kq) * 136 + wm * 32 + f * 16 + row];
                af[f][0] = __float_as_uint(Ab[0]);
                af[f][1] = __float_as_uint(Ab[8]);
                af[f][2] = __float_as_uint(Ab[4 * 136]);
                af[f][3] = __float_as_uint(Ab[4 * 136 + 8]);
            }
            uint32_t bf[2][2];
#pragma unroll
            for (int g = 0; g < 2; ++g) {
                const float* Bb = &Vs[(wn * 16 + g * 8 + row) * 132 + ks + kq];
                bf[g][0] = __float_as_uint(Bb[0]);
                bf[g][1] = __float_as_uint(Bb[4]);
            }
#pragma unroll
            for (int f = 0; f < 2; ++f)
#pragma unroll
                for (int g = 0; g < 2; ++g)
                    mma_tf32(accO[f][g], af[f], bf[g]);
        }
    }

#pragma unroll
    for (int f = 0; f < 2; ++f) {
        int rm = m0 + wm * 32 + f * 16 + row;
#pragma unroll
        for (int g = 0; g < 2; ++g) {
            int cd = wn * 16 + g * 8 + kq * 2;
            hout[(long long)bh * DL + (long long)cd * L_DIM + rm]           = cvt_tf32(fmaxf(accO[f][g][0], 0.f));
            hout[(long long)bh * DL + (long long)(cd + 1) * L_DIM + rm]     = cvt_tf32(fmaxf(accO[f][g][1], 0.f));
            hout[(long long)bh * DL + (long long)cd * L_DIM + rm + 8]       = cvt_tf32(fmaxf(accO[f][g][2], 0.f));
            hout[(long long)bh * DL + (long long)(cd + 1) * L_DIM + rm + 8] = cvt_tf32(fmaxf(accO[f][g][3], 0.f));
        }
    }
}

// ============================================================================
extern "C" void kernel_launch(void* const* d_in, const int* in_sizes, int n_in,
                              void* d_out, int out_size)
{
    (void)in_sizes; (void)n_in; (void)out_size;
    const float* x  = (const float*)d_in[0];
    const float* Wq = (const float*)d_in[1];
    const float* bq = (const float*)d_in[2];
    const float* Wk = (const float*)d_in[3];
    const float* bk = (const float*)d_in[4];
    const float* Wv = (const float*)d_in[5];
    const float* bv = (const float*)d_in[6];
    const float* W1 = (const float*)d_in[7];
    const float* b1 = (const float*)d_in[8];
    const float* W2 = (const float*)d_in[9];
    const float* b2 = (const float*)d_in[10];
    float* out = (float*)d_out;

    float *q, *k, *v, *h, *z, *mx, *is;
    float *wq, *wk, *wv, *w1, *w2, *xr;
    cudaGetSymbolAddress((void**)&q, g_q);
    cudaGetSymbolAddress((void**)&k, g_k);
    cudaGetSymbolAddress((void**)&v, g_v);
    cudaGetSymbolAddress((void**)&h, g_h);
    cudaGetSymbolAddress((void**)&z, g_z);
    cudaGetSymbolAddress((void**)&mx, g_mx);
    cudaGetSymbolAddress((void**)&is, g_is);
    cudaGetSymbolAddress((void**)&wq, g_wq);
    cudaGetSymbolAddress((void**)&wk, g_wk);
    cudaGetSymbolAddress((void**)&wv, g_wv);
    cudaGetSymbolAddress((void**)&w1, g_w1);
    cudaGetSymbolAddress((void**)&w2, g_w2);
    cudaGetSymbolAddress((void**)&xr, g_xr);

    const long long AL = (long long)A_DIM * L_DIM;
    const long long XL = (long long)CIN_DIM * L_DIM;

    const int SMEMG = 2 * (128 * 36 + 32 * 136) * 4;
    const int SMEM1 = (64 * 136 * 3) * 4;
    const int SMEM2 = (64 * 136 + 64 * 132 + 64 * 136 + 128 * 136) * 4;
    cudaFuncSetAttribute(gemm_tc<EPI_BIAS, true>,      cudaFuncAttributeMaxDynamicSharedMemorySize, SMEMG);
    cudaFuncSetAttribute(gemm_tc<EPI_BIAS_RELU, true>, cudaFuncAttributeMaxDynamicSharedMemorySize, SMEMG);
    cudaFuncSetAttribute(gemm_tc<EPI_BIAS, false>,     cudaFuncAttributeMaxDynamicSharedMemorySize, SMEMG);
    cudaFuncSetAttribute(attn_stats, cudaFuncAttributeMaxDynamicSharedMemorySize, SMEM1);
    cudaFuncSetAttribute(attn_out,   cudaFuncAttributeMaxDynamicSharedMemorySize, SMEM2);

    // 0) Pre-round GEMM operands
    const int WPROJ = A_DIM * CIN_DIM;
    const int WMLP  = A_DIM * A_DIM;
    const int XN    = B_DIM * CIN_DIM * L_DIM;
    round_copy<<<WPROJ / 1024, 256>>>(Wq, wq, WPROJ);
    round_copy<<<WPROJ / 1024, 256>>>(Wk, wk, WPROJ);
    round_copy<<<WPROJ / 1024, 256>>>(Wv, wv, WPROJ);
    round_copy<<<WMLP / 1024, 256>>>(W1, w1, WMLP);
    round_copy<<<WMLP / 1024, 256>>>(W2, w2, WMLP);
    round_copy<<<XN / 1024, 256>>>(x, xr, XN);

    // 1) QKV projections
    dim3 gproj(L_DIM / 128, A_DIM / 128, B_DIM);
    gemm_tc<EPI_BIAS, true><<<gproj, 256, SMEMG>>>(wq, xr, bq, q, A_DIM, L_DIM, CIN_DIM, 0, XL, AL);
    gemm_tc<EPI_BIAS, true><<<gproj, 256, SMEMG>>>(wk, xr, bk, k, A_DIM, L_DIM, CIN_DIM, 0, XL, AL);
    gemm_tc<EPI_BIAS, true><<<gproj, 256, SMEMG>>>(wv, xr, bv, v, A_DIM, L_DIM, CIN_DIM, 0, XL, AL);

    // 2) Fused banded attention
    attn_stats<<<dim3(8, BH_DIM), 256, SMEM1>>>(q, k, mx, is);
    attn_out<<<dim3(8, BH_DIM), 512, SMEM2>>>(q, k, v, mx, is, h);

    // 3) Final MLP
    dim3 gf(L_DIM / 128, A_DIM / 128, B_DIM);
    gemm_tc<EPI_BIAS_RELU, true><<<gf, 256, SMEMG>>>(w1, h, b1, z, A_DIM, L_DIM, A_DIM, 0, AL, AL);
    gemm_tc<EPI_BIAS, false><<<gf, 256, SMEMG>>>(w2, z, b2, out, A_DIM, L_DIM, A_DIM, 0, AL, AL);
}